// round 6
// baseline (speedup 1.0000x reference)
#include <cuda_runtime.h>

#define TW 32
#define TH 64
#define HALO 5
#define RW (TW + 2*HALO)      // 42
#define RH (TH + 2*HALO)      // 74
#define NT 256
#define IMG 512
#define PLANE (IMG*IMG)
#define CH 32                 // raw chunk rows
#define RST 44                // raw row stride (float2)

#define SSIM_C1 0.0001f
#define SSIM_C2 0.0009f

// smem: float2 raw[CH*RST] = 11264 B ; float4 hb[RH*TW] = 37888 B
#define SMEM_BYTES (CH*RST*8 + RH*TW*16)   // 49152 -> 4 CTAs/SM

// 11-tap gaussian, sigma=1.5, normalized; symmetric
__device__ __forceinline__ constexpr float wk(int k) {
    constexpr float W6[6] = { 0.00102838f, 0.00759876f, 0.03600077f,
                              0.10936078f, 0.21300553f, 0.26601171f };
    return W6[k < 6 ? k : 10 - k];
}

__global__ void __launch_bounds__(NT, 4)
ssim_kernel(const float* __restrict__ x, const float* __restrict__ y,
            float* __restrict__ out)
{
    extern __shared__ float smem[];
    float2* raw = (float2*)smem;                 // CH*RST
    float4* hb  = (float4*)(smem + CH*RST*2);    // RH*TW, {hx,hy,hs,hxy}

    const int tid   = threadIdx.x;
    const int bx    = blockIdx.x;                // 0..15
    const int by    = blockIdx.y;                // 0..7
    const int plane = blockIdx.z;                // 0..47

    const float* __restrict__ xp = x + (size_t)plane * PLANE;
    const float* __restrict__ yp = y + (size_t)plane * PLANE;

    const int gx0 = bx * TW - HALO;
    const int gy0 = by * TH - HALO;

    const bool interior = (gx0 >= 0) & (gy0 >= 0) &
                          (gx0 + RW <= IMG) & (gy0 + RH <= IMG);

    // ===== Stages 1+2: chunked raw load + horizontal blur =================
    const int hrow = tid >> 3;          // 0..31 : chunk-local row for hblur
    const int hg   = (tid & 7) * 4;     // col group

    #pragma unroll
    for (int cb = 0; cb < RH; cb += CH) {
        const int cn = (RH - cb) < CH ? (RH - cb) : CH;

        // ---- raw chunk: gmem -> smem (coalesced) ----
        if (interior) {
            for (int i = tid; i < cn * RW; i += NT) {
                int r = i / RW;
                int c = i - r * RW;
                int off = (gy0 + cb + r) * IMG + (gx0 + c);
                raw[r*RST + c] = make_float2(__ldg(xp + off), __ldg(yp + off));
            }
        } else {
            for (int i = tid; i < cn * RW; i += NT) {
                int r = i / RW;
                int c = i - r * RW;
                int gr = gy0 + cb + r, gc = gx0 + c;
                float xv = 0.f, yv = 0.f;
                if ((unsigned)gr < (unsigned)IMG && (unsigned)gc < (unsigned)IMG) {
                    int off = gr * IMG + gc;
                    xv = __ldg(xp + off);
                    yv = __ldg(yp + off);
                }
                raw[r*RST + c] = make_float2(xv, yv);
            }
        }
        __syncthreads();

        // ---- horizontal 11-tap on 4 quantities, 4 cols/thread ----
        if (hrow < cn) {
            const float2* rp = raw + hrow * RST + hg;

            float a0[4] = {0,0,0,0};   // hblur(x)
            float a1[4] = {0,0,0,0};   // hblur(y)
            float a2[4] = {0,0,0,0};   // hblur(x^2+y^2)
            float a3[4] = {0,0,0,0};   // hblur(x*y)

            #pragma unroll
            for (int p = 0; p < 14; ++p) {
                float2 v = rp[p];
                float  s  = fmaf(v.y, v.y, v.x * v.x);
                float  xy = v.x * v.y;
                #pragma unroll
                for (int i2 = 0; i2 < 4; ++i2) {
                    int k = p - i2;
                    if (k >= 0 && k <= 10) {
                        a0[i2] = fmaf(v.x, wk(k), a0[i2]);
                        a1[i2] = fmaf(v.y, wk(k), a1[i2]);
                        a2[i2] = fmaf(s,   wk(k), a2[i2]);
                        a3[i2] = fmaf(xy,  wk(k), a3[i2]);
                    }
                }
            }

            float4* hp = hb + (cb + hrow) * TW + hg;
            #pragma unroll
            for (int i2 = 0; i2 < 4; ++i2)
                hp[i2] = make_float4(a0[i2], a1[i2], a2[i2], a3[i2]);
        }
        __syncthreads();   // protect raw before next chunk / hb before stage3
    }

    // ===== Stage 3: vertical 11-tap, 8-row blocks, AoS LDS.128 ============
    {
        const int col = tid & 31;
        const int r0  = (tid >> 5) * 8;      // 8 segments * 8 rows

        float b0[8], b1[8], b2[8], b3[8];
        #pragma unroll
        for (int i2 = 0; i2 < 8; ++i2) {
            b0[i2]=0.f; b1[i2]=0.f; b2[i2]=0.f; b3[i2]=0.f;
        }

        const float4* hp = hb + r0 * TW + col;
        #pragma unroll
        for (int p = 0; p < 18; ++p) {
            float4 h = hp[p * TW];
            #pragma unroll
            for (int i2 = 0; i2 < 8; ++i2) {
                int k = p - i2;
                if (k >= 0 && k <= 10) {
                    b0[i2] = fmaf(h.x, wk(k), b0[i2]);
                    b1[i2] = fmaf(h.y, wk(k), b1[i2]);
                    b2[i2] = fmaf(h.z, wk(k), b2[i2]);
                    b3[i2] = fmaf(h.w, wk(k), b3[i2]);
                }
            }
        }

        float* op = out + (size_t)plane * PLANE
                        + (size_t)(by * TH + r0) * IMG
                        + bx * TW + col;

        #pragma unroll
        for (int i2 = 0; i2 < 8; ++i2) {
            float mu1   = b0[i2];
            float mu2   = b1[i2];
            float m12   = mu1 * mu2;
            float m11   = mu1 * mu1;
            float m22   = mu2 * mu2;
            float ssum  = b2[i2] - m11 - m22;    // sigma1^2 + sigma2^2
            float s12   = b3[i2] - m12;
            float num = fmaf(2.f, m12, SSIM_C1) * fmaf(2.f, s12, SSIM_C2);
            float den = (m11 + m22 + SSIM_C1) * (ssum + SSIM_C2);
            op[(size_t)i2 * IMG] = __fdividef(num, den);
        }
    }
}

extern "C" void kernel_launch(void* const* d_in, const int* in_sizes, int n_in,
                              void* d_out, int out_size)
{
    const float* x = (const float*)d_in[0];   // img_out  [16,3,512,512] f32
    const float* y = (const float*)d_in[1];   // img_target
    float* out = (float*)d_out;

    int planes = in_sizes[0] / PLANE;         // 48

    cudaFuncSetAttribute(ssim_kernel,
                         cudaFuncAttributeMaxDynamicSharedMemorySize,
                         SMEM_BYTES);

    dim3 grid(IMG / TW, IMG / TH, planes);    // (16, 8, 48)
    ssim_kernel<<<grid, NT, SMEM_BYTES>>>(x, y, out);
}

// round 7
// speedup vs baseline: 1.3913x; 1.3913x over previous
#include <cuda_runtime.h>

#define TW 32
#define TH 64
#define HALO 5
#define RW (TW + 2*HALO)      // 42
#define RH (TH + 2*HALO)      // 74
#define NT 256
#define IMG 512
#define PLANE (IMG*IMG)

#define SSIM_C1 0.0001f
#define SSIM_C2 0.0009f

// smem: float2 raw[RH*RW] (24864 B) + 4 hb planes [RH*TW] (37888 B) = 62752 B
#define RAW_N (RH*RW)
#define HB_N  (RH*TW)
#define SMEM_BYTES (RAW_N*8 + 4*HB_N*4)

// 11-tap gaussian, sigma=1.5, normalized; symmetric
__device__ __forceinline__ constexpr float wk(int k) {
    constexpr float W6[6] = { 0.00102838f, 0.00759876f, 0.03600077f,
                              0.10936078f, 0.21300553f, 0.26601171f };
    return W6[k < 6 ? k : 10 - k];
}

__global__ void __launch_bounds__(NT, 3)
ssim_kernel(const float* __restrict__ x, const float* __restrict__ y,
            float* __restrict__ out)
{
    extern __shared__ float smem[];
    float2* raw = (float2*)smem;            // RH*RW
    float*  hb  = smem + RAW_N*2;           // 4 * HB_N planes: x, y, x2+y2, xy

    const int tid   = threadIdx.x;
    const int bx    = blockIdx.x;           // 0..15
    const int by    = blockIdx.y;           // 0..7
    const int plane = blockIdx.z;           // 0..47

    const float* __restrict__ xp = x + (size_t)plane * PLANE;
    const float* __restrict__ yp = y + (size_t)plane * PLANE;

    const int gx0 = bx * TW - HALO;
    const int gy0 = by * TH - HALO;

    // ---------------- Stage 1: gmem -> smem raw tile ----------------------
    const bool interior = (gx0 >= 0) & (gy0 >= 0) &
                          (gx0 + RW <= IMG) & (gy0 + RH <= IMG);
    if (interior) {
        #pragma unroll 4
        for (int i = tid; i < RAW_N; i += NT) {
            int r = i / RW;
            int c = i - r * RW;
            int off = (gy0 + r) * IMG + (gx0 + c);
            raw[i] = make_float2(__ldg(xp + off), __ldg(yp + off));
        }
    } else {
        #pragma unroll 4
        for (int i = tid; i < RAW_N; i += NT) {
            int r = i / RW;
            int c = i - r * RW;
            int gr = gy0 + r, gc = gx0 + c;
            float xv = 0.f, yv = 0.f;
            if ((unsigned)gr < (unsigned)IMG && (unsigned)gc < (unsigned)IMG) {
                int off = gr * IMG + gc;
                xv = __ldg(xp + off);
                yv = __ldg(yp + off);
            }
            raw[i] = make_float2(xv, yv);
        }
    }
    __syncthreads();

    // ---------------- Stage 2: horizontal 11-tap, 4-col register block ----
    // tasks: RH rows * 8 groups of 4 cols = 592
    for (int t = tid; t < RH*(TW/4); t += NT) {
        const int row = t >> 3;
        const int g   = (t & 7) * 4;
        const float2* rp = raw + row * RW + g;

        float a0[4] = {0,0,0,0};   // hblur(x)
        float a1[4] = {0,0,0,0};   // hblur(y)
        float a2[4] = {0,0,0,0};   // hblur(x^2 + y^2)
        float a3[4] = {0,0,0,0};   // hblur(x*y)

        #pragma unroll
        for (int p = 0; p < 14; ++p) {
            float2 v = rp[p];
            float  s  = fmaf(v.y, v.y, v.x * v.x);
            float  xy = v.x * v.y;
            #pragma unroll
            for (int i2 = 0; i2 < 4; ++i2) {
                int k = p - i2;
                if (k >= 0 && k <= 10) {
                    a0[i2] = fmaf(v.x, wk(k), a0[i2]);
                    a1[i2] = fmaf(v.y, wk(k), a1[i2]);
                    a2[i2] = fmaf(s,   wk(k), a2[i2]);
                    a3[i2] = fmaf(xy,  wk(k), a3[i2]);
                }
            }
        }

        float* h = hb + row * TW + g;
        #pragma unroll
        for (int i2 = 0; i2 < 4; ++i2) {
            h[i2 + 0*HB_N] = a0[i2];
            h[i2 + 1*HB_N] = a1[i2];
            h[i2 + 2*HB_N] = a2[i2];
            h[i2 + 3*HB_N] = a3[i2];
        }
    }
    __syncthreads();

    // ---------------- Stage 3: vertical 11-tap, 8-row register block ------
    {
        const int col = tid & 31;
        const int r0  = (tid >> 5) * 8;     // 8 segments * 8 rows = 64

        float b0[8], b1[8], b2[8], b3[8];
        #pragma unroll
        for (int i2 = 0; i2 < 8; ++i2) {
            b0[i2] = 0.f; b1[i2] = 0.f; b2[i2] = 0.f; b3[i2] = 0.f;
        }

        const float* hcol = hb + col;
        #pragma unroll
        for (int p = 0; p < 18; ++p) {
            const int idx = (r0 + p) * TW;
            float h0 = hcol[0*HB_N + idx];
            float h1 = hcol[1*HB_N + idx];
            float h2 = hcol[2*HB_N + idx];
            float h3 = hcol[3*HB_N + idx];
            #pragma unroll
            for (int i2 = 0; i2 < 8; ++i2) {
                int k = p - i2;
                if (k >= 0 && k <= 10) {
                    b0[i2] = fmaf(h0, wk(k), b0[i2]);
                    b1[i2] = fmaf(h1, wk(k), b1[i2]);
                    b2[i2] = fmaf(h2, wk(k), b2[i2]);
                    b3[i2] = fmaf(h3, wk(k), b3[i2]);
                }
            }
        }

        float* op = out + (size_t)plane * PLANE
                        + (size_t)(by * TH + r0) * IMG
                        + bx * TW + col;

        #pragma unroll
        for (int i2 = 0; i2 < 8; ++i2) {
            float mu1  = b0[i2];
            float mu2  = b1[i2];
            float m12  = mu1 * mu2;
            float m11  = mu1 * mu1;
            float m22  = mu2 * mu2;
            float ssum = b2[i2] - m11 - m22;    // sigma1^2 + sigma2^2
            float s12  = b3[i2] - m12;
            float num = fmaf(2.f, m12, SSIM_C1) * fmaf(2.f, s12, SSIM_C2);
            float den = (m11 + m22 + SSIM_C1) * (ssum + SSIM_C2);
            op[(size_t)i2 * IMG] = __fdividef(num, den);
        }
    }
}

extern "C" void kernel_launch(void* const* d_in, const int* in_sizes, int n_in,
                              void* d_out, int out_size)
{
    const float* x = (const float*)d_in[0];   // img_out  [16,3,512,512] f32
    const float* y = (const float*)d_in[1];   // img_target
    float* out = (float*)d_out;

    int planes = in_sizes[0] / PLANE;         // 48

    cudaFuncSetAttribute(ssim_kernel,
                         cudaFuncAttributeMaxDynamicSharedMemorySize,
                         SMEM_BYTES);

    dim3 grid(IMG / TW, IMG / TH, planes);    // (16, 8, 48)
    ssim_kernel<<<grid, NT, SMEM_BYTES>>>(x, y, out);
}

// round 8
// speedup vs baseline: 1.4171x; 1.0186x over previous
#include <cuda_runtime.h>

#define TW 32
#define TH 64
#define HALO 5
#define RW (TW + 2*HALO)      // 42
#define RH (TH + 2*HALO)      // 74
#define NT 512
#define IMG 512
#define PLANE (IMG*IMG)

#define SSIM_C1 0.0001f
#define SSIM_C2 0.0009f

// smem: float2 raw[RH*RW] (24864 B) + 4 hb planes [RH*TW] (37888 B) = 62752 B
#define RAW_N (RH*RW)
#define HB_N  (RH*TW)
#define SMEM_BYTES (RAW_N*8 + 4*HB_N*4)

// 11-tap gaussian, sigma=1.5, normalized; symmetric
__device__ __forceinline__ constexpr float wk(int k) {
    constexpr float W6[6] = { 0.00102838f, 0.00759876f, 0.03600077f,
                              0.10936078f, 0.21300553f, 0.26601171f };
    return W6[k < 6 ? k : 10 - k];
}

__global__ void __launch_bounds__(NT, 3)
ssim_kernel(const float* __restrict__ x, const float* __restrict__ y,
            float* __restrict__ out)
{
    extern __shared__ float smem[];
    float2* raw = (float2*)smem;            // RH*RW
    float*  hb  = smem + RAW_N*2;           // 4 * HB_N planes: x, y, x2+y2, xy

    const int tid   = threadIdx.x;
    const int bx    = blockIdx.x;           // 0..15
    const int by    = blockIdx.y;           // 0..7
    const int plane = blockIdx.z;           // 0..47

    const float* __restrict__ xp = x + (size_t)plane * PLANE;
    const float* __restrict__ yp = y + (size_t)plane * PLANE;

    const int gx0 = bx * TW - HALO;
    const int gy0 = by * TH - HALO;

    // ---------------- Stage 1: gmem -> smem raw tile ----------------------
    const bool interior = (gx0 >= 0) & (gy0 >= 0) &
                          (gx0 + RW <= IMG) & (gy0 + RH <= IMG);
    if (interior) {
        #pragma unroll 3
        for (int i = tid; i < RAW_N; i += NT) {
            int r = i / RW;
            int c = i - r * RW;
            int off = (gy0 + r) * IMG + (gx0 + c);
            raw[i] = make_float2(__ldg(xp + off), __ldg(yp + off));
        }
    } else {
        #pragma unroll 3
        for (int i = tid; i < RAW_N; i += NT) {
            int r = i / RW;
            int c = i - r * RW;
            int gr = gy0 + r, gc = gx0 + c;
            float xv = 0.f, yv = 0.f;
            if ((unsigned)gr < (unsigned)IMG && (unsigned)gc < (unsigned)IMG) {
                int off = gr * IMG + gc;
                xv = __ldg(xp + off);
                yv = __ldg(yp + off);
            }
            raw[i] = make_float2(xv, yv);
        }
    }
    __syncthreads();

    // ---------------- Stage 2: horizontal 11-tap, 4-col register block ----
    // tasks: RH rows * 8 groups of 4 cols = 592
    for (int t = tid; t < RH*(TW/4); t += NT) {
        const int row = t >> 3;
        const int g   = (t & 7) * 4;
        const float2* rp = raw + row * RW + g;

        float a0[4] = {0,0,0,0};   // hblur(x)
        float a1[4] = {0,0,0,0};   // hblur(y)
        float a2[4] = {0,0,0,0};   // hblur(x^2 + y^2)
        float a3[4] = {0,0,0,0};   // hblur(x*y)

        #pragma unroll
        for (int p = 0; p < 14; ++p) {
            float2 v = rp[p];
            float  s  = fmaf(v.y, v.y, v.x * v.x);
            float  xy = v.x * v.y;
            #pragma unroll
            for (int i2 = 0; i2 < 4; ++i2) {
                int k = p - i2;
                if (k >= 0 && k <= 10) {
                    a0[i2] = fmaf(v.x, wk(k), a0[i2]);
                    a1[i2] = fmaf(v.y, wk(k), a1[i2]);
                    a2[i2] = fmaf(s,   wk(k), a2[i2]);
                    a3[i2] = fmaf(xy,  wk(k), a3[i2]);
                }
            }
        }

        float* h = hb + row * TW + g;
        #pragma unroll
        for (int i2 = 0; i2 < 4; ++i2) {
            h[i2 + 0*HB_N] = a0[i2];
            h[i2 + 1*HB_N] = a1[i2];
            h[i2 + 2*HB_N] = a2[i2];
            h[i2 + 3*HB_N] = a3[i2];
        }
    }
    __syncthreads();

    // ---------------- Stage 3: vertical 11-tap, 4-row block, 1 task/thread
    {
        const int col = tid & 31;
        const int r0  = (tid >> 5) * 4;     // 16 segments * 4 rows = 64

        float b0[4] = {0,0,0,0}, b1[4] = {0,0,0,0},
              b2[4] = {0,0,0,0}, b3[4] = {0,0,0,0};

        const float* hcol = hb + col;
        #pragma unroll
        for (int p = 0; p < 14; ++p) {
            const int idx = (r0 + p) * TW;
            float h0 = hcol[0*HB_N + idx];
            float h1 = hcol[1*HB_N + idx];
            float h2 = hcol[2*HB_N + idx];
            float h3 = hcol[3*HB_N + idx];
            #pragma unroll
            for (int i2 = 0; i2 < 4; ++i2) {
                int k = p - i2;
                if (k >= 0 && k <= 10) {
                    b0[i2] = fmaf(h0, wk(k), b0[i2]);
                    b1[i2] = fmaf(h1, wk(k), b1[i2]);
                    b2[i2] = fmaf(h2, wk(k), b2[i2]);
                    b3[i2] = fmaf(h3, wk(k), b3[i2]);
                }
            }
        }

        float* op = out + (size_t)plane * PLANE
                        + (size_t)(by * TH + r0) * IMG
                        + bx * TW + col;

        #pragma unroll
        for (int i2 = 0; i2 < 4; ++i2) {
            float mu1  = b0[i2];
            float mu2  = b1[i2];
            float m12  = mu1 * mu2;
            float m11  = mu1 * mu1;
            float m22  = mu2 * mu2;
            float ssum = b2[i2] - m11 - m22;    // sigma1^2 + sigma2^2
            float s12  = b3[i2] - m12;
            float num = fmaf(2.f, m12, SSIM_C1) * fmaf(2.f, s12, SSIM_C2);
            float den = (m11 + m22 + SSIM_C1) * (ssum + SSIM_C2);
            op[(size_t)i2 * IMG] = __fdividef(num, den);
        }
    }
}

extern "C" void kernel_launch(void* const* d_in, const int* in_sizes, int n_in,
                              void* d_out, int out_size)
{
    const float* x = (const float*)d_in[0];   // img_out  [16,3,512,512] f32
    const float* y = (const float*)d_in[1];   // img_target
    float* out = (float*)d_out;

    int planes = in_sizes[0] / PLANE;         // 48

    cudaFuncSetAttribute(ssim_kernel,
                         cudaFuncAttributeMaxDynamicSharedMemorySize,
                         SMEM_BYTES);

    dim3 grid(IMG / TW, IMG / TH, planes);    // (16, 8, 48)
    ssim_kernel<<<grid, NT, SMEM_BYTES>>>(x, y, out);
}